// round 2
// baseline (speedup 1.0000x reference)
#include <cuda_runtime.h>
#include <cuda_bf16.h>
#include <float.h>
#include <stdint.h>

#define G_N 8
#define T_N 4096
#define H_N 1024
#define E_N 32
#define C_N 64
#define ROWS (G_N*T_N)                      // 32768
#define NSLOT (G_N*E_N*C_N)                 // 16384
static const size_t NTOT = (size_t)G_N*T_N*E_N*C_N;   // 67108864

// ---------------- scratch (no allocs allowed) ----------------
__device__ float g_probs[ROWS*E_N];         // 4 MB: softmax probs [row][e]
__device__ float g_gate[NSLOT];
__device__ int   g_idx[NSLOT];
__device__ float g_zsum;

__global__ void zinit_kernel() { g_zsum = 0.0f; }

// ---------------- packed fp32x2 helpers (asm: immune to fast-math) -----------
__device__ __forceinline__ unsigned long long ffma2(unsigned long long a,
                                                    unsigned long long b,
                                                    unsigned long long c) {
    unsigned long long d;
    asm("fma.rn.f32x2 %0, %1, %2, %3;" : "=l"(d) : "l"(a), "l"(b), "l"(c));
    return d;
}
__device__ __forceinline__ unsigned long long fadd2(unsigned long long a,
                                                    unsigned long long b) {
    unsigned long long d;
    asm("add.rn.f32x2 %0, %1, %2;" : "=l"(d) : "l"(a), "l"(b));
    return d;
}
__device__ __forceinline__ unsigned long long fneg2(unsigned long long a) {
    return a ^ 0x8000000080000000ull;
}

// Accurate expf (<1 ulp), built only from __fmaf_rn so --use_fast_math cannot
// degrade it. Valid for the range seen here (x in ~[-30, 0]).
__device__ __forceinline__ float exp_rn(float x) {
    float t = __fmaf_rn(x, 1.4426950408889634f, 12582912.0f); // + 1.5*2^23: round to int
    float n = __fadd_rn(t, -12582912.0f);
    float f = __fmaf_rn(n, -0.693359375f, x);                  // ln2_hi (exact)
    f = __fmaf_rn(n, 2.1219444005469058e-4f, f);               // -ln2_lo
    float p = 1.9841269841e-4f;
    p = __fmaf_rn(p, f, 1.3888888889e-3f);
    p = __fmaf_rn(p, f, 8.3333333333e-3f);
    p = __fmaf_rn(p, f, 4.1666666667e-2f);
    p = __fmaf_rn(p, f, 1.6666666667e-1f);
    p = __fmaf_rn(p, f, 0.5f);
    p = __fmaf_rn(p, f, 1.0f);
    p = __fmaf_rn(p, f, 1.0f);
    int ei = (int)n;
    float sc = __int_as_float((ei + 127) << 23);               // exact 2^n scale
    return p * sc;
}

// ---------------- GEMM + softmax + z-loss ----------------
// Block: 256 threads, 64 rows. rloc = tid>>2, equad = tid&3 -> experts
// [equad*8, equad*8+8). 512 blocks. Accumulation: per 64-K chunk, 2 interleaved
// sub-accumulators; chunk sums folded into Kahan (s, comp). All packed f32x2.
#define KT 64
__global__ __launch_bounds__(256) void gemm_softmax_kernel(
    const float* __restrict__ x, const float* __restrict__ W,
    const float* __restrict__ bias)
{
    __shared__ __align__(16) float shx[64][68];   // pad 68: conflict-free
    __shared__ __align__(16) float shw[KT][E_N];
    __shared__ float shz[64];

    int tid  = threadIdx.x;
    int row0 = blockIdx.x * 64;
    int rloc = tid >> 2;
    int e0   = (tid & 3) * 8;

    unsigned long long ksum[4] = {0ull,0ull,0ull,0ull};   // Kahan sum
    unsigned long long kcmp[4] = {0ull,0ull,0ull,0ull};   // Kahan compensation

    for (int kt = 0; kt < H_N; kt += KT) {
        // x tile: 64 rows x 64 k = 1024 float4, coalesced
        #pragma unroll
        for (int i = 0; i < 4; i++) {
            int j  = i * 256 + tid;
            int r  = j >> 4;
            int k4 = j & 15;
            float4 v = *(const float4*)(x + (size_t)(row0 + r) * H_N + kt + k4 * 4);
            *(float4*)&shx[r][k4 * 4] = v;
        }
        // W tile: 64 k x 32 e = 512 float4
        #pragma unroll
        for (int i = 0; i < 2; i++) {
            int j  = i * 256 + tid;
            int kk = j >> 3;
            int e4 = j & 7;
            *(float4*)&shw[kk][e4 * 4] =
                *(const float4*)(W + (size_t)(kt + kk) * E_N + e4 * 4);
        }
        __syncthreads();

        unsigned long long a0[4] = {0ull,0ull,0ull,0ull};
        unsigned long long a1[4] = {0ull,0ull,0ull,0ull};
        #pragma unroll 8
        for (int k = 0; k < KT; k += 2) {
            unsigned int xi0 = __float_as_uint(shx[rloc][k]);
            unsigned int xi1 = __float_as_uint(shx[rloc][k + 1]);
            unsigned long long xx0, xx1;
            asm("mov.b64 %0, {%1, %1};" : "=l"(xx0) : "r"(xi0));
            asm("mov.b64 %0, {%1, %1};" : "=l"(xx1) : "r"(xi1));
            ulonglong2 w00 = *(const ulonglong2*)&shw[k][e0];
            ulonglong2 w01 = *(const ulonglong2*)&shw[k][e0 + 4];
            ulonglong2 w10 = *(const ulonglong2*)&shw[k + 1][e0];
            ulonglong2 w11 = *(const ulonglong2*)&shw[k + 1][e0 + 4];
            a0[0] = ffma2(xx0, w00.x, a0[0]);
            a0[1] = ffma2(xx0, w00.y, a0[1]);
            a0[2] = ffma2(xx0, w01.x, a0[2]);
            a0[3] = ffma2(xx0, w01.y, a0[3]);
            a1[0] = ffma2(xx1, w10.x, a1[0]);
            a1[1] = ffma2(xx1, w10.y, a1[1]);
            a1[2] = ffma2(xx1, w11.x, a1[2]);
            a1[3] = ffma2(xx1, w11.y, a1[3]);
        }
        // fold chunk sum into Kahan accumulator
        #pragma unroll
        for (int j = 0; j < 4; j++) {
            unsigned long long ch = fadd2(a0[j], a1[j]);
            unsigned long long y  = fadd2(ch, fneg2(kcmp[j]));
            unsigned long long t  = fadd2(ksum[j], y);
            kcmp[j] = fadd2(fadd2(t, fneg2(ksum[j])), fneg2(y));
            ksum[j] = t;
        }
        __syncthreads();
    }

    // final value = sum + comp (Neumaier correction), unpack, add bias
    float l[8];
    #pragma unroll
    for (int j = 0; j < 4; j++) {
        unsigned long long v = fadd2(ksum[j], kcmp[j]);
        l[2*j]   = __uint_as_float((unsigned int)(v & 0xffffffffull));
        l[2*j+1] = __uint_as_float((unsigned int)(v >> 32));
    }
    #pragma unroll
    for (int e = 0; e < 8; e++) l[e] = __fadd_rn(l[e], bias[e0 + e]);

    // softmax over 32 experts: local 8 + quad butterfly
    float m = l[0];
    #pragma unroll
    for (int e = 1; e < 8; e++) m = fmaxf(m, l[e]);
    m = fmaxf(m, __shfl_xor_sync(0xffffffffu, m, 1));
    m = fmaxf(m, __shfl_xor_sync(0xffffffffu, m, 2));

    float p[8], ssum = 0.f;
    #pragma unroll
    for (int e = 0; e < 8; e++) { p[e] = exp_rn(__fadd_rn(l[e], -m)); ssum = __fadd_rn(ssum, p[e]); }
    ssum = __fadd_rn(ssum, __shfl_xor_sync(0xffffffffu, ssum, 1));
    ssum = __fadd_rn(ssum, __shfl_xor_sync(0xffffffffu, ssum, 2));

    int row = row0 + rloc;
    float o[8];
    #pragma unroll
    for (int e = 0; e < 8; e++) o[e] = __fdiv_rn(p[e], ssum);   // IEEE div, like exp/sum
    float4 o0 = make_float4(o[0], o[1], o[2], o[3]);
    float4 o1 = make_float4(o[4], o[5], o[6], o[7]);
    *(float4*)&g_probs[(size_t)row * E_N + e0]     = o0;
    *(float4*)&g_probs[(size_t)row * E_N + e0 + 4] = o1;

    // z-loss partial: log_z = m + log(ssum), one lane per row
    if ((tid & 3) == 0) { float lz = m + logf(ssum); shz[rloc] = lz * lz; }
    __syncthreads();
    if (tid < 32) {
        float v = shz[tid] + shz[tid + 32];
        #pragma unroll
        for (int off = 16; off; off >>= 1)
            v += __shfl_down_sync(0xffffffffu, v, off);
        if (tid == 0) atomicAdd(&g_zsum, v);
    }
}

// ---------------- per-(g,e) top-64 over T=4096 ----------------
__global__ __launch_bounds__(256) void topk_kernel()
{
    __shared__ float vals[T_N];
    __shared__ float wrv[8];
    __shared__ int   wri[8];

    int bid = blockIdx.x;            // 0..255
    int g   = bid >> 5;
    int e   = bid & 31;
    int tid  = threadIdx.x;
    int lane = tid & 31;
    int wid  = tid >> 5;

    const float* base = g_probs + (size_t)g * T_N * E_N + e;
    for (int t = tid; t < T_N; t += 256)
        vals[t] = base[(size_t)t * E_N];
    __syncthreads();

    for (int c = 0; c < C_N; c++) {
        float bv = -FLT_MAX;
        int   bi = 0x7fffffff;
        for (int t = tid; t < T_N; t += 256) {
            float v = vals[t];
            if (v > bv) { bv = v; bi = t; }      // ascending t: strict > keeps lowest idx
        }
        #pragma unroll
        for (int off = 16; off; off >>= 1) {
            float ov = __shfl_down_sync(0xffffffffu, bv, off);
            int   oi = __shfl_down_sync(0xffffffffu, bi, off);
            if (ov > bv || (ov == bv && oi < bi)) { bv = ov; bi = oi; }
        }
        if (lane == 0) { wrv[wid] = bv; wri[wid] = bi; }
        __syncthreads();
        if (tid == 0) {
            float fv = wrv[0]; int fi = wri[0];
            #pragma unroll
            for (int w = 1; w < 8; w++) {
                float ov = wrv[w]; int oi = wri[w];
                if (ov > fv || (ov == fv && oi < fi)) { fv = ov; fi = oi; }
            }
            int gi = bid * C_N + c;
            g_gate[gi] = fv;
            g_idx[gi]  = fi;
            vals[fi]   = -FLT_MAX;   // remove winner
        }
        __syncthreads();
    }
}

// ---------------- scatter nonzeros + z-loss ----------------
__global__ __launch_bounds__(256) void scatter_kernel(float* __restrict__ out)
{
    int i = blockIdx.x * 256 + threadIdx.x;   // 0..16383
    if (i < NSLOT) {
        int c  = i & 63;
        int ge = i >> 6;
        int e  = ge & 31;
        int g  = ge >> 5;
        int t  = g_idx[i];
        float gate = g_gate[i];
        size_t off = (((size_t)g * T_N + t) * E_N + e) * C_N + c;
        out[off]        = gate;    // combine
        out[NTOT + off] = 1.0f;    // dispatch
    }
    if (i == 0)
        out[2 * NTOT] = g_zsum * (1.0f / (float)(G_N * T_N));  // z_loss
}

// ---------------- launch ----------------
extern "C" void kernel_launch(void* const* d_in, const int* in_sizes, int n_in,
                              void* d_out, int out_size)
{
    const float* x = (const float*)d_in[0];   // [G,T,H] fp32
    const float* W = (const float*)d_in[1];   // [H,E]  fp32
    const float* b = (const float*)d_in[2];   // [E]    fp32
    float* out = (float*)d_out;

    // zero the full output (combine + dispatch are ~sparse one-hots)
    cudaMemsetAsync(out, 0, (size_t)out_size * sizeof(float), 0);

    zinit_kernel<<<1, 1>>>();
    gemm_softmax_kernel<<<ROWS / 64, 256>>>(x, W, b);
    topk_kernel<<<G_N * E_N, 256>>>();
    scatter_kernel<<<(NSLOT + 255) / 256, 256>>>(out);
}

// round 3
// speedup vs baseline: 1.0475x; 1.0475x over previous
#include <cuda_runtime.h>
#include <cuda_bf16.h>
#include <float.h>
#include <stdint.h>

#define G_N 8
#define T_N 4096
#define H_N 1024
#define E_N 32
#define C_N 64
#define ROWS (G_N*T_N)                      // 32768
#define NSLOT (G_N*E_N*C_N)                 // 16384
#define GEMM_BLOCKS 128                     // 256 rows per block
static const size_t NTOT = (size_t)G_N*T_N*E_N*C_N;   // 67108864

// ---------------- scratch (no allocs allowed) ----------------
__device__ float g_probsT[E_N*ROWS];        // 4 MB: probs transposed [g][e][t]
__device__ float g_gate[NSLOT];
__device__ int   g_idx[NSLOT];
__device__ float g_zpart[GEMM_BLOCKS];

// ---------------- packed fp32x2 helpers (asm: immune to fast-math) -----------
__device__ __forceinline__ unsigned long long ffma2(unsigned long long a,
                                                    unsigned long long b,
                                                    unsigned long long c) {
    unsigned long long d;
    asm("fma.rn.f32x2 %0, %1, %2, %3;" : "=l"(d) : "l"(a), "l"(b), "l"(c));
    return d;
}
__device__ __forceinline__ unsigned long long fadd2(unsigned long long a,
                                                    unsigned long long b) {
    unsigned long long d;
    asm("add.rn.f32x2 %0, %1, %2;" : "=l"(d) : "l"(a), "l"(b));
    return d;
}
__device__ __forceinline__ unsigned long long fneg2(unsigned long long a) {
    return a ^ 0x8000000080000000ull;
}
__device__ __forceinline__ unsigned long long splat2(float x) {
    unsigned long long d; unsigned int xi = __float_as_uint(x);
    asm("mov.b64 %0, {%1, %1};" : "=l"(d) : "r"(xi));
    return d;
}

// Accurate expf (<1 ulp) built from __fmaf_rn only (fast-math-proof).
__device__ __forceinline__ float exp_rn(float x) {
    float t = __fmaf_rn(x, 1.4426950408889634f, 12582912.0f);
    float n = __fadd_rn(t, -12582912.0f);
    float f = __fmaf_rn(n, -0.693359375f, x);
    f = __fmaf_rn(n, 2.1219444005469058e-4f, f);
    float p = 1.9841269841e-4f;
    p = __fmaf_rn(p, f, 1.3888888889e-3f);
    p = __fmaf_rn(p, f, 8.3333333333e-3f);
    p = __fmaf_rn(p, f, 4.1666666667e-2f);
    p = __fmaf_rn(p, f, 1.6666666667e-1f);
    p = __fmaf_rn(p, f, 0.5f);
    p = __fmaf_rn(p, f, 1.0f);
    p = __fmaf_rn(p, f, 1.0f);
    int ei = (int)n;
    float sc = __int_as_float((ei + 127) << 23);
    return p * sc;
}

// ---------------- GEMM + softmax + z-loss ----------------
// grid 128, block 256. Thread: eq = tid&3 -> experts [eq*8, eq*8+8),
// rg = tid>>2 -> 4 rows {rg, rg+64, rg+128, rg+192} of the 256-row tile.
// K chunked by 32; per-chunk plain accumulator folded into Kahan (sum,comp).
#define KT 32
#define XS 36   // shx row stride (pad): mod 32 = 4 -> conflict-free reads
__global__ __launch_bounds__(256) void gemm_softmax_kernel(
    const float* __restrict__ x, const float* __restrict__ W,
    const float* __restrict__ bias)
{
    __shared__ __align__(16) float shx[256 * XS];   // 36.9 KB
    __shared__ __align__(16) float shw[KT * E_N];   // 4 KB
    __shared__ float shz[8];

    int tid  = threadIdx.x;
    int row0 = blockIdx.x * 256;
    int eq   = tid & 3;
    int rg   = tid >> 2;
    int e0   = eq * 8;

    unsigned long long ksum[4][4], kcmp[4][4];
    #pragma unroll
    for (int r = 0; r < 4; r++)
        #pragma unroll
        for (int j = 0; j < 4; j++) { ksum[r][j] = 0ull; kcmp[r][j] = 0ull; }

    for (int kt = 0; kt < H_N; kt += KT) {
        // x tile: 256 rows x 32 k = 2048 float4, coalesced (8 per thread)
        #pragma unroll
        for (int i = 0; i < 8; i++) {
            int j  = i * 256 + tid;
            int r  = j >> 3;
            int k4 = j & 7;
            float4 v = *(const float4*)(x + (size_t)(row0 + r) * H_N + kt + k4 * 4);
            *(float4*)&shx[r * XS + k4 * 4] = v;
        }
        // W tile: 32 k x 32 e = 256 float4 (1 per thread)
        {
            int kk = tid >> 3;
            int e4 = tid & 7;
            *(float4*)&shw[kk * E_N + e4 * 4] =
                *(const float4*)(W + (size_t)(kt + kk) * E_N + e4 * 4);
        }
        __syncthreads();

        unsigned long long a[4][4];
        #pragma unroll
        for (int r = 0; r < 4; r++)
            #pragma unroll
            for (int j = 0; j < 4; j++) a[r][j] = 0ull;

        #pragma unroll 8
        for (int kk = 0; kk < KT; kk++) {
            unsigned long long xx[4];
            #pragma unroll
            for (int r = 0; r < 4; r++)
                xx[r] = splat2(shx[(rg + 64 * r) * XS + kk]);
            ulonglong2 w0 = *(const ulonglong2*)&shw[kk * E_N + e0];
            ulonglong2 w1 = *(const ulonglong2*)&shw[kk * E_N + e0 + 4];
            #pragma unroll
            for (int r = 0; r < 4; r++) {
                a[r][0] = ffma2(xx[r], w0.x, a[r][0]);
                a[r][1] = ffma2(xx[r], w0.y, a[r][1]);
                a[r][2] = ffma2(xx[r], w1.x, a[r][2]);
                a[r][3] = ffma2(xx[r], w1.y, a[r][3]);
            }
        }
        // Kahan fold of chunk sums
        #pragma unroll
        for (int r = 0; r < 4; r++)
            #pragma unroll
            for (int j = 0; j < 4; j++) {
                unsigned long long y = fadd2(a[r][j], fneg2(kcmp[r][j]));
                unsigned long long t = fadd2(ksum[r][j], y);
                kcmp[r][j] = fadd2(fadd2(t, fneg2(ksum[r][j])), fneg2(y));
                ksum[r][j] = t;
            }
        __syncthreads();
    }

    // epilogue: per row r -> logits, softmax, transposed store, z partial
    float zacc = 0.0f;
    float bv[8];
    #pragma unroll
    for (int e = 0; e < 8; e++) bv[e] = bias[e0 + e];

    #pragma unroll
    for (int r = 0; r < 4; r++) {
        float l[8];
        #pragma unroll
        for (int j = 0; j < 4; j++) {
            unsigned long long v = fadd2(ksum[r][j], kcmp[r][j]);
            l[2*j]   = __uint_as_float((unsigned int)(v & 0xffffffffull));
            l[2*j+1] = __uint_as_float((unsigned int)(v >> 32));
        }
        #pragma unroll
        for (int e = 0; e < 8; e++) l[e] = __fadd_rn(l[e], bv[e]);

        float m = l[0];
        #pragma unroll
        for (int e = 1; e < 8; e++) m = fmaxf(m, l[e]);
        m = fmaxf(m, __shfl_xor_sync(0xffffffffu, m, 1));
        m = fmaxf(m, __shfl_xor_sync(0xffffffffu, m, 2));

        float p[8], s = 0.f;
        #pragma unroll
        for (int e = 0; e < 8; e++) { p[e] = exp_rn(__fadd_rn(l[e], -m)); s = __fadd_rn(s, p[e]); }
        s = __fadd_rn(s, __shfl_xor_sync(0xffffffffu, s, 1));
        s = __fadd_rn(s, __shfl_xor_sync(0xffffffffu, s, 2));

        int grow = row0 + rg + 64 * r;
        int g    = grow >> 12;
        int t    = grow & (T_N - 1);
        float* dst = g_probsT + ((size_t)g * E_N + e0) * T_N + t;
        #pragma unroll
        for (int e = 0; e < 8; e++)
            dst[(size_t)e * T_N] = __fdiv_rn(p[e], s);   // IEEE div

        float lz = m + logf(s);
        zacc = __fmaf_rn(lz, lz, zacc);
    }

    // block z reduce: only eq==0 lanes hold valid zacc
    float v = (eq == 0) ? zacc : 0.0f;
    #pragma unroll
    for (int off = 16; off; off >>= 1)
        v += __shfl_xor_sync(0xffffffffu, v, off);
    if ((tid & 31) == 0) shz[tid >> 5] = v;
    __syncthreads();
    if (tid == 0) {
        float zs = 0.f;
        #pragma unroll
        for (int w = 0; w < 8; w++) zs += shz[w];
        g_zpart[blockIdx.x] = zs;
    }
}

// ---------------- per-(g,e) top-64 over T=4096 ----------------
__global__ __launch_bounds__(256) void topk_kernel()
{
    __shared__ float vals[T_N];
    __shared__ float wrv[8];
    __shared__ int   wri[8];

    int bid = blockIdx.x;            // 0..255 = g*32 + e
    int tid  = threadIdx.x;
    int lane = tid & 31;
    int wid  = tid >> 5;

    // coalesced load of the contiguous [t] row
    const float4* base = (const float4*)(g_probsT + (size_t)bid * T_N);
    #pragma unroll
    for (int i = 0; i < 4; i++)
        *(float4*)&vals[(i * 256 + tid) * 4] = base[i * 256 + tid];
    __syncthreads();

    for (int c = 0; c < C_N; c++) {
        float bv = -FLT_MAX;
        int   bi = 0x7fffffff;
        #pragma unroll 4
        for (int t = tid; t < T_N; t += 256) {
            float v = vals[t];
            if (v > bv) { bv = v; bi = t; }      // ascending t: strict > keeps lowest idx
        }
        #pragma unroll
        for (int off = 16; off; off >>= 1) {
            float ov = __shfl_down_sync(0xffffffffu, bv, off);
            int   oi = __shfl_down_sync(0xffffffffu, bi, off);
            if (ov > bv || (ov == bv && oi < bi)) { bv = ov; bi = oi; }
        }
        if (lane == 0) { wrv[wid] = bv; wri[wid] = bi; }
        __syncthreads();
        if (tid == 0) {
            float fv = wrv[0]; int fi = wri[0];
            #pragma unroll
            for (int w = 1; w < 8; w++) {
                float ov = wrv[w]; int oi = wri[w];
                if (ov > fv || (ov == fv && oi < fi)) { fv = ov; fi = oi; }
            }
            int gi = bid * C_N + c;
            g_gate[gi] = fv;
            g_idx[gi]  = fi;
            vals[fi]   = -FLT_MAX;
        }
        __syncthreads();
    }
}

// ---------------- scatter nonzeros + z-loss ----------------
__global__ __launch_bounds__(256) void scatter_kernel(float* __restrict__ out)
{
    __shared__ float red[8];
    int i = blockIdx.x * 256 + threadIdx.x;
    if (i < NSLOT) {
        int c  = i & 63;
        int ge = i >> 6;
        int e  = ge & 31;
        int g  = ge >> 5;
        int t  = g_idx[i];
        float gate = g_gate[i];
        size_t off = (((size_t)g * T_N + t) * E_N + e) * C_N + c;
        out[off]        = gate;    // combine
        out[NTOT + off] = 1.0f;    // dispatch
    }
    if (blockIdx.x == 0) {
        int tid = threadIdx.x;
        float v = (tid < GEMM_BLOCKS) ? g_zpart[tid] : 0.0f;
        #pragma unroll
        for (int off = 16; off; off >>= 1)
            v += __shfl_xor_sync(0xffffffffu, v, off);
        if ((tid & 31) == 0) red[tid >> 5] = v;
        __syncthreads();
        if (tid == 0) {
            float zs = 0.f;
            #pragma unroll
            for (int w = 0; w < 8; w++) zs += red[w];
            out[2 * NTOT] = zs * (1.0f / (float)(G_N * T_N));
        }
    }
}

// ---------------- launch ----------------
extern "C" void kernel_launch(void* const* d_in, const int* in_sizes, int n_in,
                              void* d_out, int out_size)
{
    const float* x = (const float*)d_in[0];   // [G,T,H] fp32
    const float* W = (const float*)d_in[1];   // [H,E]  fp32
    const float* b = (const float*)d_in[2];   // [E]    fp32
    float* out = (float*)d_out;

    static cudaStream_t s_mem = nullptr;
    static cudaEvent_t ev_fork = nullptr, ev_join = nullptr;
    if (s_mem == nullptr) {
        cudaStreamCreateWithFlags(&s_mem, cudaStreamNonBlocking);
        cudaEventCreateWithFlags(&ev_fork, cudaEventDisableTiming);
        cudaEventCreateWithFlags(&ev_join, cudaEventDisableTiming);
    }

    // fork: memset runs on s_mem concurrently with gemm+topk on stream 0
    cudaEventRecord(ev_fork, 0);
    cudaStreamWaitEvent(s_mem, ev_fork, 0);
    cudaMemsetAsync(out, 0, (size_t)out_size * sizeof(float), s_mem);
    cudaEventRecord(ev_join, s_mem);

    gemm_softmax_kernel<<<GEMM_BLOCKS, 256>>>(x, W, b);
    topk_kernel<<<G_N * E_N, 256>>>();

    // join: scatter needs both the zeroed output and topk results
    cudaStreamWaitEvent(0, ev_join, 0);
    scatter_kernel<<<(NSLOT + 255) / 256, 256>>>(out);
}

// round 5
// speedup vs baseline: 1.3413x; 1.2805x over previous
#include <cuda_runtime.h>
#include <cuda_bf16.h>
#include <float.h>
#include <stdint.h>

#define G_N 8
#define T_N 4096
#define H_N 1024
#define E_N 32
#define C_N 64
#define ROWS (G_N*T_N)                      // 32768
#define NSLOT (G_N*E_N*C_N)                 // 16384
#define BR 64                               // rows per gemm block
#define GEMM_BLOCKS (ROWS/BR)               // 512
static const size_t NTOT = (size_t)G_N*T_N*E_N*C_N;   // 67108864

// ---------------- scratch (no allocs allowed) ----------------
__device__ float g_probsT[E_N*ROWS];        // 4 MB: probs transposed [g][e][t]
__device__ float g_gate[NSLOT];
__device__ int   g_idx[NSLOT];
__device__ float g_zpart[GEMM_BLOCKS];

// ---------------- packed fp32x2 helpers (asm: immune to fast-math) -----------
__device__ __forceinline__ unsigned long long ffma2(unsigned long long a,
                                                    unsigned long long b,
                                                    unsigned long long c) {
    unsigned long long d;
    asm("fma.rn.f32x2 %0, %1, %2, %3;" : "=l"(d) : "l"(a), "l"(b), "l"(c));
    return d;
}
__device__ __forceinline__ unsigned long long fadd2(unsigned long long a,
                                                    unsigned long long b) {
    unsigned long long d;
    asm("add.rn.f32x2 %0, %1, %2;" : "=l"(d) : "l"(a), "l"(b));
    return d;
}
__device__ __forceinline__ unsigned long long fneg2(unsigned long long a) {
    return a ^ 0x8000000080000000ull;
}
__device__ __forceinline__ unsigned long long splat2(float x) {
    unsigned long long d; unsigned int xi = __float_as_uint(x);
    asm("mov.b64 %0, {%1, %1};" : "=l"(d) : "r"(xi));
    return d;
}

// Accurate expf (<1 ulp) built from __fmaf_rn only (fast-math-proof).
__device__ __forceinline__ float exp_rn(float x) {
    float t = __fmaf_rn(x, 1.4426950408889634f, 12582912.0f);
    float n = __fadd_rn(t, -12582912.0f);
    float f = __fmaf_rn(n, -0.693359375f, x);
    f = __fmaf_rn(n, 2.1219444005469058e-4f, f);
    float p = 1.9841269841e-4f;
    p = __fmaf_rn(p, f, 1.3888888889e-3f);
    p = __fmaf_rn(p, f, 8.3333333333e-3f);
    p = __fmaf_rn(p, f, 4.1666666667e-2f);
    p = __fmaf_rn(p, f, 1.6666666667e-1f);
    p = __fmaf_rn(p, f, 0.5f);
    p = __fmaf_rn(p, f, 1.0f);
    p = __fmaf_rn(p, f, 1.0f);
    int ei = (int)n;
    float sc = __int_as_float((ei + 127) << 23);
    return p * sc;
}

// ---------------- GEMM + softmax + z-loss ----------------
// grid 512, block 128. eq = tid&3 -> experts [eq*8, eq*8+8),
// rg = tid>>2 in [0,32) -> rows {rg, rg+32}. Register-double-buffered tile
// pipeline: prefetch tile kt+1 LDGs issued before consuming tile kt from smem.
// K chunked by 32; per-chunk accumulator folded into Kahan (sum, comp).
#define KT 32
#define XS 36   // shx row stride (pad): conflict-free broadcast reads
__global__ __launch_bounds__(128) void gemm_softmax_kernel(
    const float* __restrict__ x, const float* __restrict__ W,
    const float* __restrict__ bias)
{
    __shared__ __align__(16) float shx[BR * XS];    // 9.2 KB
    __shared__ __align__(16) float shw[KT * E_N];   // 4 KB
    __shared__ float shz[4];

    int tid  = threadIdx.x;
    int row0 = blockIdx.x * BR;
    int eq   = tid & 3;
    int rg   = tid >> 2;        // 0..31
    int e0   = eq * 8;

    unsigned long long ksum[2][4], kcmp[2][4];
    #pragma unroll
    for (int r = 0; r < 2; r++)
        #pragma unroll
        for (int j = 0; j < 4; j++) { ksum[r][j] = 0ull; kcmp[r][j] = 0ull; }

    // prefetch registers: x tile 64x32 = 512 float4 (4/thr), W 32x32 = 256 float4 (2/thr)
    float4 px[4], pw[2];
    #pragma unroll
    for (int i = 0; i < 4; i++) {
        int j = i * 128 + tid;
        px[i] = *(const float4*)(x + (size_t)(row0 + (j >> 3)) * H_N + (j & 7) * 4);
    }
    #pragma unroll
    for (int i = 0; i < 2; i++) {
        int j = i * 128 + tid;
        pw[i] = *(const float4*)(W + (size_t)(j >> 3) * E_N + (j & 7) * 4);
    }

    for (int kt = 0; kt < H_N; kt += KT) {
        // commit prefetched tile to smem
        #pragma unroll
        for (int i = 0; i < 4; i++) {
            int j = i * 128 + tid;
            *(float4*)&shx[(j >> 3) * XS + (j & 7) * 4] = px[i];
        }
        #pragma unroll
        for (int i = 0; i < 2; i++) {
            int j = i * 128 + tid;
            *(float4*)&shw[(j >> 3) * E_N + (j & 7) * 4] = pw[i];
        }
        __syncthreads();

        // issue next tile's LDGs (overlap DRAM with compute below)
        int ktn = (kt + KT < H_N) ? kt + KT : 0;
        #pragma unroll
        for (int i = 0; i < 4; i++) {
            int j = i * 128 + tid;
            px[i] = *(const float4*)(x + (size_t)(row0 + (j >> 3)) * H_N + ktn + (j & 7) * 4);
        }
        #pragma unroll
        for (int i = 0; i < 2; i++) {
            int j = i * 128 + tid;
            pw[i] = *(const float4*)(W + (size_t)(ktn + (j >> 3)) * E_N + (j & 7) * 4);
        }

        unsigned long long a[2][4];
        #pragma unroll
        for (int r = 0; r < 2; r++)
            #pragma unroll
            for (int j = 0; j < 4; j++) a[r][j] = 0ull;

        #pragma unroll 8
        for (int kk = 0; kk < KT; kk++) {
            unsigned long long x0 = splat2(shx[rg * XS + kk]);
            unsigned long long x1 = splat2(shx[(rg + 32) * XS + kk]);
            ulonglong2 w0 = *(const ulonglong2*)&shw[kk * E_N + e0];
            ulonglong2 w1 = *(const ulonglong2*)&shw[kk * E_N + e0 + 4];
            a[0][0] = ffma2(x0, w0.x, a[0][0]);
            a[0][1] = ffma2(x0, w0.y, a[0][1]);
            a[0][2] = ffma2(x0, w1.x, a[0][2]);
            a[0][3] = ffma2(x0, w1.y, a[0][3]);
            a[1][0] = ffma2(x1, w0.x, a[1][0]);
            a[1][1] = ffma2(x1, w0.y, a[1][1]);
            a[1][2] = ffma2(x1, w1.x, a[1][2]);
            a[1][3] = ffma2(x1, w1.y, a[1][3]);
        }
        // Kahan fold of chunk sums
        #pragma unroll
        for (int r = 0; r < 2; r++)
            #pragma unroll
            for (int j = 0; j < 4; j++) {
                unsigned long long y = fadd2(a[r][j], fneg2(kcmp[r][j]));
                unsigned long long t = fadd2(ksum[r][j], y);
                kcmp[r][j] = fadd2(fadd2(t, fneg2(ksum[r][j])), fneg2(y));
                ksum[r][j] = t;
            }
        __syncthreads();
    }

    // epilogue: per row -> logits, softmax, transposed store, z partial
    float zacc = 0.0f;
    float bv[8];
    #pragma unroll
    for (int e = 0; e < 8; e++) bv[e] = bias[e0 + e];

    #pragma unroll
    for (int r = 0; r < 2; r++) {
        float l[8];
        #pragma unroll
        for (int j = 0; j < 4; j++) {
            unsigned long long v = fadd2(ksum[r][j], kcmp[r][j]);
            l[2*j]   = __uint_as_float((unsigned int)(v & 0xffffffffull));
            l[2*j+1] = __uint_as_float((unsigned int)(v >> 32));
        }
        #pragma unroll
        for (int e = 0; e < 8; e++) l[e] = __fadd_rn(l[e], bv[e]);

        float m = l[0];
        #pragma unroll
        for (int e = 1; e < 8; e++) m = fmaxf(m, l[e]);
        m = fmaxf(m, __shfl_xor_sync(0xffffffffu, m, 1));
        m = fmaxf(m, __shfl_xor_sync(0xffffffffu, m, 2));

        float p[8], s = 0.f;
        #pragma unroll
        for (int e = 0; e < 8; e++) { p[e] = exp_rn(__fadd_rn(l[e], -m)); s = __fadd_rn(s, p[e]); }
        s = __fadd_rn(s, __shfl_xor_sync(0xffffffffu, s, 1));
        s = __fadd_rn(s, __shfl_xor_sync(0xffffffffu, s, 2));

        int grow = row0 + rg + 32 * r;
        int g    = grow >> 12;
        int t    = grow & (T_N - 1);
        float* dst = g_probsT + ((size_t)g * E_N + e0) * T_N + t;
        #pragma unroll
        for (int e = 0; e < 8; e++)
            dst[(size_t)e * T_N] = __fdiv_rn(p[e], s);   // IEEE div

        float lz = m + logf(s);
        zacc = __fmaf_rn(lz, lz, zacc);
    }

    // block z reduce: only eq==0 lanes hold valid zacc
    float v = (eq == 0) ? zacc : 0.0f;
    #pragma unroll
    for (int off = 16; off; off >>= 1)
        v += __shfl_xor_sync(0xffffffffu, v, off);
    if ((tid & 31) == 0) shz[tid >> 5] = v;
    __syncthreads();
    if (tid == 0) {
        float zs = 0.f;
        #pragma unroll
        for (int w = 0; w < 4; w++) zs += shz[w];
        g_zpart[blockIdx.x] = zs;
    }
}

// ---------------- per-(g,e) top-64 over T=4096 ----------------
// Cached-best iterative argmax: each thread owns 16 contiguous elements and
// caches its local (max, idx). Per round: block-reduce 256 cached bests; only
// the winning thread rescans its 16 elements. Tie-break = lowest index.
__global__ __launch_bounds__(256) void topk_kernel()
{
    __shared__ float vals[T_N];
    __shared__ float wrv[8];
    __shared__ int   wri[8];
    __shared__ int   swi;

    int bid  = blockIdx.x;            // 0..255 = g*32 + e
    int tid  = threadIdx.x;
    int lane = tid & 31;
    int wid  = tid >> 5;

    const float4* base = (const float4*)(g_probsT + (size_t)bid * T_N);
    float bv = -FLT_MAX;
    int   bi = 0x7fffffff;
    #pragma unroll
    for (int i = 0; i < 4; i++) {
        float4 v = base[tid * 4 + i];
        *(float4*)&vals[tid * 16 + i * 4] = v;
        int t0 = tid * 16 + i * 4;
        if (v.x > bv) { bv = v.x; bi = t0;     }
        if (v.y > bv) { bv = v.y; bi = t0 + 1; }
        if (v.z > bv) { bv = v.z; bi = t0 + 2; }
        if (v.w > bv) { bv = v.w; bi = t0 + 3; }
    }
    __syncthreads();

    for (int c = 0; c < C_N; c++) {
        float rv = bv; int ri = bi;
        #pragma unroll
        for (int off = 16; off; off >>= 1) {
            float ov = __shfl_down_sync(0xffffffffu, rv, off);
            int   oi = __shfl_down_sync(0xffffffffu, ri, off);
            if (ov > rv || (ov == rv && oi < ri)) { rv = ov; ri = oi; }
        }
        if (lane == 0) { wrv[wid] = rv; wri[wid] = ri; }
        __syncthreads();
        if (tid == 0) {
            float fv = wrv[0]; int fi = wri[0];
            #pragma unroll
            for (int w = 1; w < 8; w++) {
                float ov = wrv[w]; int oi = wri[w];
                if (ov > fv || (ov == fv && oi < fi)) { fv = ov; fi = oi; }
            }
            int gi = bid * C_N + c;
            g_gate[gi] = fv;
            g_idx[gi]  = fi;
            vals[fi]   = -FLT_MAX;   // remove winner
            swi = fi;
        }
        __syncthreads();
        int fi = swi;
        if ((fi >> 4) == tid) {      // only winner rescans its 16 elements
            bv = -FLT_MAX; bi = 0x7fffffff;
            #pragma unroll
            for (int i = 0; i < 16; i++) {
                float v = vals[tid * 16 + i];
                if (v > bv) { bv = v; bi = tid * 16 + i; }
            }
        }
    }
}

// ---------------- scatter nonzeros + z-loss ----------------
__global__ __launch_bounds__(256) void scatter_kernel(float* __restrict__ out)
{
    __shared__ float red[8];
    int i = blockIdx.x * 256 + threadIdx.x;
    if (i < NSLOT) {
        int c  = i & 63;
        int ge = i >> 6;
        int e  = ge & 31;
        int g  = ge >> 5;
        int t  = g_idx[i];
        float gate = g_gate[i];
        size_t off = (((size_t)g * T_N + t) * E_N + e) * C_N + c;
        out[off]        = gate;    // combine
        out[NTOT + off] = 1.0f;    // dispatch
    }
    if (blockIdx.x == 0) {
        int tid = threadIdx.x;
        float v = 0.0f;
        for (int j = tid; j < GEMM_BLOCKS; j += 256) v += g_zpart[j];
        #pragma unroll
        for (int off = 16; off; off >>= 1)
            v += __shfl_xor_sync(0xffffffffu, v, off);
        if ((tid & 31) == 0) red[tid >> 5] = v;
        __syncthreads();
        if (tid == 0) {
            float zs = 0.f;
            #pragma unroll
            for (int w = 0; w < 8; w++) zs += red[w];
            out[2 * NTOT] = zs * (1.0f / (float)(G_N * T_N));
        }
    }
}

// ---------------- launch ----------------
extern "C" void kernel_launch(void* const* d_in, const int* in_sizes, int n_in,
                              void* d_out, int out_size)
{
    const float* x = (const float*)d_in[0];   // [G,T,H] fp32
    const float* W = (const float*)d_in[1];   // [H,E]  fp32
    const float* b = (const float*)d_in[2];   // [E]    fp32
    float* out = (float*)d_out;

    static cudaStream_t s_mem = nullptr;
    static cudaEvent_t ev_fork = nullptr, ev_join = nullptr;
    if (s_mem == nullptr) {
        cudaStreamCreateWithFlags(&s_mem, cudaStreamNonBlocking);
        cudaEventCreateWithFlags(&ev_fork, cudaEventDisableTiming);
        cudaEventCreateWithFlags(&ev_join, cudaEventDisableTiming);
    }

    // fork: memset runs on s_mem concurrently with gemm+topk on stream 0
    cudaEventRecord(ev_fork, 0);
    cudaStreamWaitEvent(s_mem, ev_fork, 0);
    cudaMemsetAsync(out, 0, (size_t)out_size * sizeof(float), s_mem);
    cudaEventRecord(ev_join, s_mem);

    gemm_softmax_kernel<<<GEMM_BLOCKS, 128>>>(x, W, b);
    topk_kernel<<<G_N * E_N, 256>>>();

    // join: scatter needs both the zeroed output and topk results
    cudaStreamWaitEvent(0, ev_join, 0);
    scatter_kernel<<<(NSLOT + 255) / 256, 256>>>(out);
}

// round 7
// speedup vs baseline: 1.8027x; 1.3440x over previous
#include <cuda_runtime.h>
#include <cuda_bf16.h>
#include <float.h>
#include <stdint.h>

#define G_N 8
#define T_N 4096
#define H_N 1024
#define E_N 32
#define C_N 64
#define ROWS (G_N*T_N)                      // 32768
#define NSLOT (G_N*E_N*C_N)                 // 16384
#define BR 64                               // rows per gemm block
#define GEMM_BLOCKS (ROWS/BR)               // 512
static const size_t NTOT = (size_t)G_N*T_N*E_N*C_N;   // 67108864

// ---------------- scratch (no allocs allowed) ----------------
__device__ float g_probsT[E_N*ROWS];        // 4 MB: probs transposed [g][e][t]
__device__ float g_gate[NSLOT];
__device__ int   g_idx[NSLOT];
__device__ float g_zpart[GEMM_BLOCKS];

// ---------------- packed fp32x2 helpers (asm: immune to fast-math) -----------
__device__ __forceinline__ unsigned long long ffma2(unsigned long long a,
                                                    unsigned long long b,
                                                    unsigned long long c) {
    unsigned long long d;
    asm("fma.rn.f32x2 %0, %1, %2, %3;" : "=l"(d) : "l"(a), "l"(b), "l"(c));
    return d;
}
__device__ __forceinline__ unsigned long long fadd2(unsigned long long a,
                                                    unsigned long long b) {
    unsigned long long d;
    asm("add.rn.f32x2 %0, %1, %2;" : "=l"(d) : "l"(a), "l"(b));
    return d;
}
__device__ __forceinline__ unsigned long long fneg2(unsigned long long a) {
    return a ^ 0x8000000080000000ull;
}
__device__ __forceinline__ unsigned long long splat2(float x) {
    unsigned long long d; unsigned int xi = __float_as_uint(x);
    asm("mov.b64 %0, {%1, %1};" : "=l"(d) : "r"(xi));
    return d;
}

// Accurate expf (<1 ulp) built from __fmaf_rn only (fast-math-proof).
__device__ __forceinline__ float exp_rn(float x) {
    float t = __fmaf_rn(x, 1.4426950408889634f, 12582912.0f);
    float n = __fadd_rn(t, -12582912.0f);
    float f = __fmaf_rn(n, -0.693359375f, x);
    f = __fmaf_rn(n, 2.1219444005469058e-4f, f);
    float p = 1.9841269841e-4f;
    p = __fmaf_rn(p, f, 1.3888888889e-3f);
    p = __fmaf_rn(p, f, 8.3333333333e-3f);
    p = __fmaf_rn(p, f, 4.1666666667e-2f);
    p = __fmaf_rn(p, f, 1.6666666667e-1f);
    p = __fmaf_rn(p, f, 0.5f);
    p = __fmaf_rn(p, f, 1.0f);
    p = __fmaf_rn(p, f, 1.0f);
    int ei = (int)n;
    float sc = __int_as_float((ei + 127) << 23);
    return p * sc;
}

// ---------------- GEMM + softmax + z-loss + fused output zeroing -------------
// grid 512, block 128. eq = tid&3 -> experts [eq*8, eq*8+8),
// rg = tid>>2 -> rows {rg, rg+32}. Register-double-buffered tile pipeline.
// Per k-chunk, each thread also streams 16 float4 zero-stores into d_out
// (fused memset: 512 blk x 32 chunks x 2048 f4 = 2*NTOT floats exactly).
#define KT 32
#define XS 36   // shx row stride (pad): conflict-free broadcast reads
__global__ __launch_bounds__(128) void gemm_softmax_kernel(
    const float* __restrict__ x, const float* __restrict__ W,
    const float* __restrict__ bias, float4* __restrict__ zout)
{
    __shared__ __align__(16) float shx[BR * XS];    // 9.2 KB
    __shared__ __align__(16) float shw[KT * E_N];   // 4 KB
    __shared__ float shz[4];

    int tid  = threadIdx.x;
    int row0 = blockIdx.x * BR;
    int eq   = tid & 3;
    int rg   = tid >> 2;        // 0..31
    int e0   = eq * 8;

    unsigned long long ksum[2][4], kcmp[2][4];
    #pragma unroll
    for (int r = 0; r < 2; r++)
        #pragma unroll
        for (int j = 0; j < 4; j++) { ksum[r][j] = 0ull; kcmp[r][j] = 0ull; }

    // prefetch registers
    float4 px[4], pw[2];
    #pragma unroll
    for (int i = 0; i < 4; i++) {
        int j = i * 128 + tid;
        px[i] = *(const float4*)(x + (size_t)(row0 + (j >> 3)) * H_N + (j & 7) * 4);
    }
    #pragma unroll
    for (int i = 0; i < 2; i++) {
        int j = i * 128 + tid;
        pw[i] = *(const float4*)(W + (size_t)(j >> 3) * E_N + (j & 7) * 4);
    }

    const float4 zf4 = make_float4(0.f, 0.f, 0.f, 0.f);

    for (int kt = 0; kt < H_N; kt += KT) {
        // commit prefetched tile to smem
        #pragma unroll
        for (int i = 0; i < 4; i++) {
            int j = i * 128 + tid;
            *(float4*)&shx[(j >> 3) * XS + (j & 7) * 4] = px[i];
        }
        #pragma unroll
        for (int i = 0; i < 2; i++) {
            int j = i * 128 + tid;
            *(float4*)&shw[(j >> 3) * E_N + (j & 7) * 4] = pw[i];
        }
        __syncthreads();

        // issue next tile's LDGs (overlap DRAM with compute below)
        int ktn = (kt + KT < H_N) ? kt + KT : 0;
        #pragma unroll
        for (int i = 0; i < 4; i++) {
            int j = i * 128 + tid;
            px[i] = *(const float4*)(x + (size_t)(row0 + (j >> 3)) * H_N + ktn + (j & 7) * 4);
        }
        #pragma unroll
        for (int i = 0; i < 2; i++) {
            int j = i * 128 + tid;
            pw[i] = *(const float4*)(W + (size_t)(ktn + (j >> 3)) * E_N + (j & 7) * 4);
        }

        // fused memset slice: streaming stores, fire-and-forget
        {
            size_t b4 = ((size_t)blockIdx.x * 32 + (size_t)(kt >> 5)) * 2048 + tid;
            #pragma unroll
            for (int i = 0; i < 16; i++)
                __stcs(zout + b4 + (size_t)i * 128, zf4);
        }

        unsigned long long a[2][4];
        #pragma unroll
        for (int r = 0; r < 2; r++)
            #pragma unroll
            for (int j = 0; j < 4; j++) a[r][j] = 0ull;

        #pragma unroll 8
        for (int kk = 0; kk < KT; kk++) {
            unsigned long long x0 = splat2(shx[rg * XS + kk]);
            unsigned long long x1 = splat2(shx[(rg + 32) * XS + kk]);
            ulonglong2 w0 = *(const ulonglong2*)&shw[kk * E_N + e0];
            ulonglong2 w1 = *(const ulonglong2*)&shw[kk * E_N + e0 + 4];
            a[0][0] = ffma2(x0, w0.x, a[0][0]);
            a[0][1] = ffma2(x0, w0.y, a[0][1]);
            a[0][2] = ffma2(x0, w1.x, a[0][2]);
            a[0][3] = ffma2(x0, w1.y, a[0][3]);
            a[1][0] = ffma2(x1, w0.x, a[1][0]);
            a[1][1] = ffma2(x1, w0.y, a[1][1]);
            a[1][2] = ffma2(x1, w1.x, a[1][2]);
            a[1][3] = ffma2(x1, w1.y, a[1][3]);
        }
        // Kahan fold of chunk sums
        #pragma unroll
        for (int r = 0; r < 2; r++)
            #pragma unroll
            for (int j = 0; j < 4; j++) {
                unsigned long long y = fadd2(a[r][j], fneg2(kcmp[r][j]));
                unsigned long long t = fadd2(ksum[r][j], y);
                kcmp[r][j] = fadd2(fadd2(t, fneg2(ksum[r][j])), fneg2(y));
                ksum[r][j] = t;
            }
        __syncthreads();
    }

    // epilogue: per row -> logits, softmax, transposed store, z partial
    float zacc = 0.0f;
    float bv[8];
    #pragma unroll
    for (int e = 0; e < 8; e++) bv[e] = bias[e0 + e];

    #pragma unroll
    for (int r = 0; r < 2; r++) {
        float l[8];
        #pragma unroll
        for (int j = 0; j < 4; j++) {
            unsigned long long v = fadd2(ksum[r][j], kcmp[r][j]);
            l[2*j]   = __uint_as_float((unsigned int)(v & 0xffffffffull));
            l[2*j+1] = __uint_as_float((unsigned int)(v >> 32));
        }
        #pragma unroll
        for (int e = 0; e < 8; e++) l[e] = __fadd_rn(l[e], bv[e]);

        float m = l[0];
        #pragma unroll
        for (int e = 1; e < 8; e++) m = fmaxf(m, l[e]);
        m = fmaxf(m, __shfl_xor_sync(0xffffffffu, m, 1));
        m = fmaxf(m, __shfl_xor_sync(0xffffffffu, m, 2));

        float p[8], s = 0.f;
        #pragma unroll
        for (int e = 0; e < 8; e++) { p[e] = exp_rn(__fadd_rn(l[e], -m)); s = __fadd_rn(s, p[e]); }
        s = __fadd_rn(s, __shfl_xor_sync(0xffffffffu, s, 1));
        s = __fadd_rn(s, __shfl_xor_sync(0xffffffffu, s, 2));

        int grow = row0 + rg + 32 * r;
        int g    = grow >> 12;
        int t    = grow & (T_N - 1);
        float* dst = g_probsT + ((size_t)g * E_N + e0) * T_N + t;
        #pragma unroll
        for (int e = 0; e < 8; e++)
            dst[(size_t)e * T_N] = __fdiv_rn(p[e], s);   // IEEE div

        float lz = m + logf(s);
        zacc = __fmaf_rn(lz, lz, zacc);
    }

    float v = (eq == 0) ? zacc : 0.0f;
    #pragma unroll
    for (int off = 16; off; off >>= 1)
        v += __shfl_xor_sync(0xffffffffu, v, off);
    if ((tid & 31) == 0) shz[tid >> 5] = v;
    __syncthreads();
    if (tid == 0) {
        float zs = 0.f;
        #pragma unroll
        for (int w = 0; w < 4; w++) zs += shz[w];
        g_zpart[blockIdx.x] = zs;
    }
}

// ---------------- per-(g,e) exact top-64 via 4-level radix select ------------
// Positive-float bits are order-preserving as uint32. 4x 8-bit histogram
// levels find the exact 64th-largest bit pattern; strictly-greater winners are
// compacted and ranked by composite key (bits desc, idx asc); threshold ties
// are taken by smallest index via block prefix-scan. Matches jax.lax.top_k.
__global__ __launch_bounds__(256) void topk_kernel()
{
    __shared__ unsigned int ub[T_N];           // 16 KB: prob bits
    __shared__ int hist[256];
    __shared__ int tmp[256];
    __shared__ int sel_bin, sel_krem;
    __shared__ unsigned long long glist[C_N];
    __shared__ int gcnt;

    int bid = blockIdx.x;            // 0..255 = g*32 + e
    int tid = threadIdx.x;

    const float4* base = (const float4*)(g_probsT + (size_t)bid * T_N);
    #pragma unroll
    for (int i = 0; i < 4; i++) {
        float4 v = base[tid * 4 + i];
        uint4 u;
        u.x = __float_as_uint(v.x); u.y = __float_as_uint(v.y);
        u.z = __float_as_uint(v.z); u.w = __float_as_uint(v.w);
        *(uint4*)&ub[tid * 16 + i * 4] = u;
    }
    if (tid == 0) gcnt = 0;

    unsigned int pref = 0;
    int k_rem = C_N;
    for (int lvl = 0; lvl < 4; lvl++) {
        int sh = 24 - 8 * lvl;
        hist[tid] = 0;
        __syncthreads();
        #pragma unroll
        for (int i = 0; i < 16; i++) {
            unsigned int b = ub[tid * 16 + i];
            bool cand = (lvl == 0) || ((b >> (32 - 8 * lvl)) == pref);
            if (cand) atomicAdd(&hist[(b >> sh) & 255], 1);
        }
        __syncthreads();
        // suffix sum: hist[b] <- sum_{b'>=b} hist[b']
        int sv = hist[tid];
        #pragma unroll
        for (int off = 1; off < 256; off <<= 1) {
            tmp[tid] = sv;
            __syncthreads();
            if (tid + off < 256) sv += tmp[tid + off];
            __syncthreads();
        }
        hist[tid] = sv;
        __syncthreads();
        int nxt = (tid < 255) ? hist[tid + 1] : 0;
        if (hist[tid] >= k_rem && nxt < k_rem) {
            sel_bin  = tid;
            sel_krem = k_rem - nxt;   // still needed inside this bin
        }
        __syncthreads();
        pref  = (pref << 8) | (unsigned int)sel_bin;
        k_rem = sel_krem;
        __syncthreads();
    }
    unsigned int thr = pref;         // exact 64th-largest bit pattern
    int need   = k_rem;              // how many == thr to take (smallest idx)
    int cnt_gt = C_N - need;

    // compact strictly-greater winners (unordered)
    #pragma unroll
    for (int i = 0; i < 16; i++) {
        int t = tid * 16 + i;
        unsigned int b = ub[t];
        if (b > thr) {
            int p = atomicAdd(&gcnt, 1);
            glist[p] = ((unsigned long long)b << 32) |
                       (unsigned long long)(0xFFFFFFFFu - (unsigned int)t);
        }
    }

    // equals: block exclusive scan of per-thread equal-counts (t ascending)
    int leq = 0;
    #pragma unroll
    for (int i = 0; i < 16; i++) leq += (ub[tid * 16 + i] == thr);
    int sv = leq;
    #pragma unroll
    for (int off = 1; off < 256; off <<= 1) {
        tmp[tid] = sv;
        __syncthreads();
        if (tid >= off) sv += tmp[tid - off];
        __syncthreads();
    }
    int ir = sv - leq;               // exclusive prefix = index-rank of my first equal
    #pragma unroll
    for (int i = 0; i < 16; i++) {
        int t = tid * 16 + i;
        if (ub[t] == thr) {
            if (ir < need) {
                int gi = bid * C_N + cnt_gt + ir;
                g_gate[gi] = __uint_as_float(thr);
                g_idx[gi]  = t;
            }
            ir++;
        }
    }
    __syncthreads();                 // glist/gcnt final

    // rank strictly-greater winners: slot = #keys greater than mine
    if (tid < cnt_gt) {
        unsigned long long mk = glist[tid];
        int rank = 0;
        for (int j = 0; j < cnt_gt; j++) rank += (glist[j] > mk);
        int gi = bid * C_N + rank;
        g_gate[gi] = __uint_as_float((unsigned int)(mk >> 32));
        g_idx[gi]  = (int)(0xFFFFFFFFu - (unsigned int)(mk & 0xFFFFFFFFull));
    }
}

// ---------------- scatter nonzeros + z-loss ----------------
__global__ __launch_bounds__(256) void scatter_kernel(float* __restrict__ out)
{
    __shared__ float red[8];
    int i = blockIdx.x * 256 + threadIdx.x;
    if (i < NSLOT) {
        int c  = i & 63;
        int ge = i >> 6;
        int e  = ge & 31;
        int g  = ge >> 5;
        int t  = g_idx[i];
        float gate = g_gate[i];
        size_t off = (((size_t)g * T_N + t) * E_N + e) * C_N + c;
        out[off]        = gate;    // combine
        out[NTOT + off] = 1.0f;    // dispatch
    }
    if (blockIdx.x == 0) {
        int tid = threadIdx.x;
        float v = 0.0f;
        for (int j = tid; j < GEMM_BLOCKS; j += 256) v += g_zpart[j];
        #pragma unroll
        for (int off = 16; off; off >>= 1)
            v += __shfl_xor_sync(0xffffffffu, v, off);
        if ((tid & 31) == 0) red[tid >> 5] = v;
        __syncthreads();
        if (tid == 0) {
            float zs = 0.f;
            #pragma unroll
            for (int w = 0; w < 8; w++) zs += red[w];
            out[2 * NTOT] = zs * (1.0f / (float)(G_N * T_N));
        }
    }
}

// ---------------- launch ----------------
extern "C" void kernel_launch(void* const* d_in, const int* in_sizes, int n_in,
                              void* d_out, int out_size)
{
    const float* x = (const float*)d_in[0];   // [G,T,H] fp32
    const float* W = (const float*)d_in[1];   // [H,E]  fp32
    const float* b = (const float*)d_in[2];   // [E]    fp32
    float* out = (float*)d_out;

    gemm_softmax_kernel<<<GEMM_BLOCKS, 128>>>(x, W, b, (float4*)out);
    topk_kernel<<<G_N * E_N, 256>>>();
    scatter_kernel<<<(NSLOT + 255) / 256, 256>>>(out);
}

// round 8
// speedup vs baseline: 2.0184x; 1.1196x over previous
#include <cuda_runtime.h>
#include <cuda_bf16.h>
#include <float.h>
#include <stdint.h>

#define G_N 8
#define T_N 4096
#define H_N 1024
#define E_N 32
#define C_N 64
#define ROWS (G_N*T_N)                      // 32768
#define NSLOT (G_N*E_N*C_N)                 // 16384
#define BR 64                               // rows per gemm block
#define GEMM_BLOCKS (ROWS/BR)               // 512
static const size_t NTOT = (size_t)G_N*T_N*E_N*C_N;   // 67108864

// ---------------- scratch (no allocs allowed) ----------------
__device__ float g_probsT[E_N*ROWS];        // 4 MB: probs transposed [g][e][t]
__device__ float g_zpart[GEMM_BLOCKS];

// ---------------- packed fp32x2 helpers (asm: immune to fast-math) -----------
__device__ __forceinline__ unsigned long long ffma2(unsigned long long a,
                                                    unsigned long long b,
                                                    unsigned long long c) {
    unsigned long long d;
    asm("fma.rn.f32x2 %0, %1, %2, %3;" : "=l"(d) : "l"(a), "l"(b), "l"(c));
    return d;
}
__device__ __forceinline__ unsigned long long fadd2(unsigned long long a,
                                                    unsigned long long b) {
    unsigned long long d;
    asm("add.rn.f32x2 %0, %1, %2;" : "=l"(d) : "l"(a), "l"(b));
    return d;
}
__device__ __forceinline__ unsigned long long fneg2(unsigned long long a) {
    return a ^ 0x8000000080000000ull;
}
__device__ __forceinline__ unsigned long long splat2(float x) {
    unsigned long long d; unsigned int xi = __float_as_uint(x);
    asm("mov.b64 %0, {%1, %1};" : "=l"(d) : "r"(xi));
    return d;
}
__device__ __forceinline__ uint32_t smem_u32(const void* p) {
    uint32_t a;
    asm("{ .reg .u64 t; cvta.to.shared.u64 t, %1; cvt.u32.u64 %0, t; }"
        : "=r"(a) : "l"(p));
    return a;
}

// Accurate expf (<1 ulp) built from __fmaf_rn only (fast-math-proof).
__device__ __forceinline__ float exp_rn(float x) {
    float t = __fmaf_rn(x, 1.4426950408889634f, 12582912.0f);
    float n = __fadd_rn(t, -12582912.0f);
    float f = __fmaf_rn(n, -0.693359375f, x);
    f = __fmaf_rn(n, 2.1219444005469058e-4f, f);
    float p = 1.9841269841e-4f;
    p = __fmaf_rn(p, f, 1.3888888889e-3f);
    p = __fmaf_rn(p, f, 8.3333333333e-3f);
    p = __fmaf_rn(p, f, 4.1666666667e-2f);
    p = __fmaf_rn(p, f, 1.6666666667e-1f);
    p = __fmaf_rn(p, f, 0.5f);
    p = __fmaf_rn(p, f, 1.0f);
    p = __fmaf_rn(p, f, 1.0f);
    int ei = (int)n;
    float sc = __int_as_float((ei + 127) << 23);
    return p * sc;
}

// ---------------- GEMM + softmax + z-loss + TMA-bulk output zeroing ----------
// grid 512, block 128. eq = tid&3 -> experts [eq*8, eq*8+8),
// rg = tid>>2 -> rows {rg, rg+32}. Register-double-buffered tile pipeline.
// Zero-fill: 32 KB zeroed smem buffer; one cp.async.bulk 32KB store per
// k-chunk (512 blk x 32 chunks x 32 KB = 2*NTOT floats exactly). Async engine
// drains the writes; the warp issue stream stays free for ffma2.
#define KT 32
#define XS 36   // shx row stride (pad): conflict-free broadcast reads
#define ZB_BYTES 32768
__global__ __launch_bounds__(128) void gemm_softmax_kernel(
    const float* __restrict__ x, const float* __restrict__ W,
    const float* __restrict__ bias, char* __restrict__ zout)
{
    __shared__ __align__(16) float shx[BR * XS];        // 9.2 KB
    __shared__ __align__(16) float shw[KT * E_N];       // 4 KB
    __shared__ __align__(16) float4 zbuf[ZB_BYTES/16];  // 32 KB of zeros
    __shared__ float shz[4];

    int tid  = threadIdx.x;
    int row0 = blockIdx.x * BR;
    int eq   = tid & 3;
    int rg   = tid >> 2;        // 0..31
    int e0   = eq * 8;

    // zero the TMA source buffer (16 float4 per thread)
    const float4 zf4 = make_float4(0.f, 0.f, 0.f, 0.f);
    #pragma unroll
    for (int i = 0; i < 16; i++) zbuf[i * 128 + tid] = zf4;

    unsigned long long ksum[2][4], kcmp[2][4];
    #pragma unroll
    for (int r = 0; r < 2; r++)
        #pragma unroll
        for (int j = 0; j < 4; j++) { ksum[r][j] = 0ull; kcmp[r][j] = 0ull; }

    // prefetch registers
    float4 px[4], pw[2];
    #pragma unroll
    for (int i = 0; i < 4; i++) {
        int j = i * 128 + tid;
        px[i] = *(const float4*)(x + (size_t)(row0 + (j >> 3)) * H_N + (j & 7) * 4);
    }
    #pragma unroll
    for (int i = 0; i < 2; i++) {
        int j = i * 128 + tid;
        pw[i] = *(const float4*)(W + (size_t)(j >> 3) * E_N + (j & 7) * 4);
    }

    uint32_t zb_s = smem_u32(zbuf);

    for (int kt = 0; kt < H_N; kt += KT) {
        // commit prefetched tile to smem
        #pragma unroll
        for (int i = 0; i < 4; i++) {
            int j = i * 128 + tid;
            *(float4*)&shx[(j >> 3) * XS + (j & 7) * 4] = px[i];
        }
        #pragma unroll
        for (int i = 0; i < 2; i++) {
            int j = i * 128 + tid;
            *(float4*)&shw[(j >> 3) * E_N + (j & 7) * 4] = pw[i];
        }
        __syncthreads();   // also makes zbuf zeros visible block-wide (iter 0)

        // one 32KB async bulk zero-store per chunk (elected thread)
        if (tid == 0) {
            if (kt == 0)
                asm volatile("fence.proxy.async.shared::cta;" ::: "memory");
            char* dst = zout + ((size_t)blockIdx.x * 32 + (size_t)(kt >> 5)) * ZB_BYTES;
            asm volatile(
                "cp.async.bulk.global.shared::cta.bulk_group [%0], [%1], %2;"
                :: "l"(dst), "r"(zb_s), "r"((unsigned)ZB_BYTES) : "memory");
        }

        // issue next tile's LDGs (overlap DRAM with compute below)
        int ktn = (kt + KT < H_N) ? kt + KT : 0;
        #pragma unroll
        for (int i = 0; i < 4; i++) {
            int j = i * 128 + tid;
            px[i] = *(const float4*)(x + (size_t)(row0 + (j >> 3)) * H_N + ktn + (j & 7) * 4);
        }
        #pragma unroll
        for (int i = 0; i < 2; i++) {
            int j = i * 128 + tid;
            pw[i] = *(const float4*)(W + (size_t)(ktn + (j >> 3)) * E_N + (j & 7) * 4);
        }

        unsigned long long a[2][4];
        #pragma unroll
        for (int r = 0; r < 2; r++)
            #pragma unroll
            for (int j = 0; j < 4; j++) a[r][j] = 0ull;

        #pragma unroll 8
        for (int kk = 0; kk < KT; kk++) {
            unsigned long long x0 = splat2(shx[rg * XS + kk]);
            unsigned long long x1 = splat2(shx[(rg + 32) * XS + kk]);
            ulonglong2 w0 = *(const ulonglong2*)&shw[kk * E_N + e0];
            ulonglong2 w1 = *(const ulonglong2*)&shw[kk * E_N + e0 + 4];
            a[0][0] = ffma2(x0, w0.x, a[0][0]);
            a[0][1] = ffma2(x0, w0.y, a[0][1]);
            a[0][2] = ffma2(x0, w1.x, a[0][2]);
            a[0][3] = ffma2(x0, w1.y, a[0][3]);
            a[1][0] = ffma2(x1, w0.x, a[1][0]);
            a[1][1] = ffma2(x1, w0.y, a[1][1]);
            a[1][2] = ffma2(x1, w1.x, a[1][2]);
            a[1][3] = ffma2(x1, w1.y, a[1][3]);
        }
        // Kahan fold of chunk sums
        #pragma unroll
        for (int r = 0; r < 2; r++)
            #pragma unroll
            for (int j = 0; j < 4; j++) {
                unsigned long long y = fadd2(a[r][j], fneg2(kcmp[r][j]));
                unsigned long long t = fadd2(ksum[r][j], y);
                kcmp[r][j] = fadd2(fadd2(t, fneg2(ksum[r][j])), fneg2(y));
                ksum[r][j] = t;
            }
        __syncthreads();
    }

    // epilogue: per row -> logits, softmax, transposed store, z partial
    float zacc = 0.0f;
    float bv[8];
    #pragma unroll
    for (int e = 0; e < 8; e++) bv[e] = bias[e0 + e];

    #pragma unroll
    for (int r = 0; r < 2; r++) {
        float l[8];
        #pragma unroll
        for (int j = 0; j < 4; j++) {
            unsigned long long v = fadd2(ksum[r][j], kcmp[r][j]);
            l[2*j]   = __uint_as_float((unsigned int)(v & 0xffffffffull));
            l[2*j+1] = __uint_as_float((unsigned int)(v >> 32));
        }
        #pragma unroll
        for (int e = 0; e < 8; e++) l[e] = __fadd_rn(l[e], bv[e]);

        float m = l[0];
        #pragma unroll
        for (int e = 1; e < 8; e++) m = fmaxf(m, l[e]);
        m = fmaxf(m, __shfl_xor_sync(0xffffffffu, m, 1));
        m = fmaxf(m, __shfl_xor_sync(0xffffffffu, m, 2));

        float p[8], s = 0.f;
        #pragma unroll
        for (int e = 0; e < 8; e++) { p[e] = exp_rn(__fadd_rn(l[e], -m)); s = __fadd_rn(s, p[e]); }
        s = __fadd_rn(s, __shfl_xor_sync(0xffffffffu, s, 1));
        s = __fadd_rn(s, __shfl_xor_sync(0xffffffffu, s, 2));

        int grow = row0 + rg + 32 * r;
        int g    = grow >> 12;
        int t    = grow & (T_N - 1);
        float* dst = g_probsT + ((size_t)g * E_N + e0) * T_N + t;
        #pragma unroll
        for (int e = 0; e < 8; e++)
            dst[(size_t)e * T_N] = __fdiv_rn(p[e], s);   // IEEE div

        float lz = m + logf(s);
        zacc = __fmaf_rn(lz, lz, zacc);
    }

    float v = (eq == 0) ? zacc : 0.0f;
    #pragma unroll
    for (int off = 16; off; off >>= 1)
        v += __shfl_xor_sync(0xffffffffu, v, off);
    if ((tid & 31) == 0) shz[tid >> 5] = v;
    __syncthreads();
    if (tid == 0) {
        float zs = 0.f;
        #pragma unroll
        for (int w = 0; w < 4; w++) zs += shz[w];
        g_zpart[blockIdx.x] = zs;
        // drain async zero-stores before kernel exit (visibility for topk)
        asm volatile("cp.async.bulk.commit_group;" ::: "memory");
        asm volatile("cp.async.bulk.wait_group 0;" ::: "memory");
    }
}

// ------- per-(g,e) exact top-64 via 4-level radix select + fused scatter -----
// Positive-float bits are order-preserving as uint32. 4x 8-bit histogram
// levels find the exact 64th-largest bit pattern; strictly-greater winners are
// ranked by composite key (bits desc, idx asc); threshold ties taken by
// smallest index via block prefix-scan (= jax.lax.top_k). Winners are written
// straight into the (pre-zeroed) combine/dispatch outputs; block 0 adds z_loss.
__global__ __launch_bounds__(256) void topk_kernel(float* __restrict__ out)
{
    __shared__ unsigned int ub[T_N];           // 16 KB: prob bits
    __shared__ int hist[256];
    __shared__ int tmp[256];
    __shared__ int sel_bin, sel_krem;
    __shared__ unsigned long long glist[C_N];
    __shared__ int gcnt;
    __shared__ float red[8];

    int bid = blockIdx.x;            // 0..255 = g*32 + e
    int g   = bid >> 5;
    int e   = bid & 31;
    int tid = threadIdx.x;

    const float4* base = (const float4*)(g_probsT + (size_t)bid * T_N);
    #pragma unroll
    for (int i = 0; i < 4; i++) {
        float4 v = base[tid * 4 + i];
        uint4 u;
        u.x = __float_as_uint(v.x); u.y = __float_as_uint(v.y);
        u.z = __float_as_uint(v.z); u.w = __float_as_uint(v.w);
        *(uint4*)&ub[tid * 16 + i * 4] = u;
    }
    if (tid == 0) gcnt = 0;

    unsigned int pref = 0;
    int k_rem = C_N;
    for (int lvl = 0; lvl < 4; lvl++) {
        int sh = 24 - 8 * lvl;
        hist[tid] = 0;
        __syncthreads();
        #pragma unroll
        for (int i = 0; i < 16; i++) {
            unsigned int b = ub[tid * 16 + i];
            bool cand = (lvl == 0) || ((b >> (32 - 8 * lvl)) == pref);
            if (cand) atomicAdd(&hist[(b >> sh) & 255], 1);
        }
        __syncthreads();
        // suffix sum: hist[b] <- sum_{b'>=b} hist[b']
        int sv = hist[tid];
        #pragma unroll
        for (int off = 1; off < 256; off <<= 1) {
            tmp[tid] = sv;
            __syncthreads();
            if (tid + off < 256) sv += tmp[tid + off];
            __syncthreads();
        }
        hist[tid] = sv;
        __syncthreads();
        int nxt = (tid < 255) ? hist[tid + 1] : 0;
        if (hist[tid] >= k_rem && nxt < k_rem) {
            sel_bin  = tid;
            sel_krem = k_rem - nxt;
        }
        __syncthreads();
        pref  = (pref << 8) | (unsigned int)sel_bin;
        k_rem = sel_krem;
        __syncthreads();
    }
    unsigned int thr = pref;         // exact 64th-largest bit pattern
    int need   = k_rem;              // how many == thr to take (smallest idx)
    int cnt_gt = C_N - need;

    const size_t ge_off = ((size_t)g * T_N) * (E_N * C_N) + (size_t)e * C_N;

    // compact strictly-greater winners (unordered)
    #pragma unroll
    for (int i = 0; i < 16; i++) {
        int t = tid * 16 + i;
        unsigned int b = ub[t];
        if (b > thr) {
            int p = atomicAdd(&gcnt, 1);
            glist[p] = ((unsigned long long)b << 32) |
                       (unsigned long long)(0xFFFFFFFFu - (unsigned int)t);
        }
    }

    // equals: block exclusive scan of per-thread equal-counts (t ascending)
    int leq = 0;
    #pragma unroll
    for (int i = 0; i < 16; i++) leq += (ub[tid * 16 + i] == thr);
    int sv = leq;
    #pragma unroll
    for (int off = 1; off < 256; off <<= 1) {
        tmp[tid] = sv;
        __syncthreads();
        if (tid >= off) sv += tmp[tid - off];
        __syncthreads();
    }
    int ir = sv - leq;
    #pragma unroll
    for (int i = 0; i < 16; i++) {
        int t = tid * 16 + i;
        if (ub[t] == thr) {
            if (ir < need) {
                size_t off = ge_off + (size_t)t * (E_N * C_N) + (cnt_gt + ir);
                out[off]        = __uint_as_float(thr);   // combine
                out[NTOT + off] = 1.0f;                   // dispatch
            }
            ir++;
        }
    }
    __syncthreads();                 // glist/gcnt final

    // rank strictly-greater winners: slot = #keys greater than mine
    if (tid < cnt_gt) {
        unsigned long long mk = glist[tid];
        int rank = 0;
        for (int j = 0; j < cnt_gt; j++) rank += (glist[j] > mk);
        int t = (int)(0xFFFFFFFFu - (unsigned int)(mk & 0xFFFFFFFFull));
        size_t off = ge_off + (size_t)t * (E_N * C_N) + rank;
        out[off]        = __uint_as_float((unsigned int)(mk >> 32));
        out[NTOT + off] = 1.0f;
    }

    // z-loss (block 0)
    if (bid == 0) {
        float v = 0.0f;
        for (int j = tid; j < GEMM_BLOCKS; j += 256) v += g_zpart[j];
        #pragma unroll
        for (int off = 16; off; off >>= 1)
            v += __shfl_xor_sync(0xffffffffu, v, off);
        if ((tid & 31) == 0) red[tid >> 5] = v;
        __syncthreads();
        if (tid == 0) {
            float zs = 0.f;
            #pragma unroll
            for (int w = 0; w < 8; w++) zs += red[w];
            out[2 * NTOT] = zs * (1.0f / (float)(G_N * T_N));
        }
    }
}

// ---------------- launch ----------------
extern "C" void kernel_launch(void* const* d_in, const int* in_sizes, int n_in,
                              void* d_out, int out_size)
{
    const float* x = (const float*)d_in[0];   // [G,T,H] fp32
    const float* W = (const float*)d_in[1];   // [H,E]  fp32
    const float* b = (const float*)d_in[2];   // [E]    fp32
    float* out = (float*)d_out;

    gemm_softmax_kernel<<<GEMM_BLOCKS, 128>>>(x, W, b, (char*)out);
    topk_kernel<<<G_N * E_N, 256>>>(out);
}